// round 1
// baseline (speedup 1.0000x reference)
#include <cuda_runtime.h>

// MS-SSIM loss, 4 scales, fused separable-Gaussian SSIM + avg-pool per scale.
// Input: img1, img2 float32 [16,3,512,512]. Output: scalar float32.

#define TW 32
#define TH 32
#define HALO 5
#define IW (TW + 2*HALO)   // 42
#define IH (TH + 2*HALO)   // 42
#define IPITCH 44
#define HPITCH (TW + 1)    // 33
#define NPLANES 48         // 16*3

// ---- scratch (static device globals; no allocations allowed) ----
__device__ float g_acc[4];
__device__ float g_p1a[48 * 256 * 256];
__device__ float g_p1b[48 * 256 * 256];
__device__ float g_p2a[48 * 128 * 128];
__device__ float g_p2b[48 * 128 * 128];
__device__ float g_p3a[48 * 64 * 64];
__device__ float g_p3b[48 * 64 * 64];

__global__ void init_acc_kernel() {
    if (threadIdx.x < 4) g_acc[threadIdx.x] = 0.0f;
}

__global__ void __launch_bounds__(256)
ssim_kernel(const float* __restrict__ A0, const float* __restrict__ B0,
            int scale, int W, int do_pool)
{
    __shared__ float sA[IH][IPITCH];
    __shared__ float sB[IH][IPITCH];
    __shared__ float hbuf[5][IH][HPITCH];
    __shared__ float red[8];

    // Gaussian(11, sigma=1.5), normalized. Compile-time constants so the
    // unrolled tap loops emit FFMA-imm (rt_SMSP=1).
    const float G[11] = {
        0.00102838f, 0.00759875f, 0.03600077f, 0.10936070f, 0.21300553f,
        0.26601172f,
        0.21300553f, 0.10936070f, 0.03600077f, 0.00759875f, 0.00102838f };

    const int H = W;
    const float* A;
    const float* B;
    switch (scale) {
        case 0:  A = A0;     B = B0;     break;
        case 1:  A = g_p1a;  B = g_p1b;  break;
        case 2:  A = g_p2a;  B = g_p2b;  break;
        default: A = g_p3a;  B = g_p3b;  break;
    }

    const int tx = blockIdx.x * TW;
    const int ty = blockIdx.y * TH;
    const int plane = blockIdx.z;
    const size_t pbase = (size_t)plane * (size_t)W * (size_t)H;
    const int tid = threadIdx.x;

    // ---- stage 1: load (TH+10)x(TW+10) tile of both images, zero-padded ----
    for (int i = tid; i < IH * IW; i += 256) {
        int r = i / IW;
        int c = i - r * IW;
        int gy = ty + r - HALO;
        int gx = tx + c - HALO;
        float va = 0.0f, vb = 0.0f;
        if ((unsigned)gy < (unsigned)H && (unsigned)gx < (unsigned)W) {
            size_t idx = pbase + (size_t)gy * W + gx;
            va = A[idx];
            vb = B[idx];
        }
        sA[r][c] = va;
        sB[r][c] = vb;
    }
    __syncthreads();

    // ---- fused 2x2 avg-pool for next scale (reads the already-loaded tile) ----
    if (do_pool) {
        int pr = tid >> 4;       // 0..15
        int pc = tid & 15;       // 0..15
        int r = HALO + 2 * pr;
        int c = HALO + 2 * pc;
        float pa = 0.25f * (sA[r][c] + sA[r][c + 1] + sA[r + 1][c] + sA[r + 1][c + 1]);
        float pb = 0.25f * (sB[r][c] + sB[r][c + 1] + sB[r + 1][c] + sB[r + 1][c + 1]);
        int pW = W >> 1;
        size_t pidx = (size_t)plane * pW * pW + (size_t)((ty >> 1) + pr) * pW + ((tx >> 1) + pc);
        float* PA;
        float* PB;
        switch (scale) {
            case 0:  PA = g_p1a; PB = g_p1b; break;
            case 1:  PA = g_p2a; PB = g_p2b; break;
            default: PA = g_p3a; PB = g_p3b; break;
        }
        PA[pidx] = pa;
        PB[pidx] = pb;
    }

    // ---- stage 2: horizontal 11-tap pass over all IH rows, TW cols ----
    // 5 channels: mu1, mu2, E[x1^2], E[x2^2], E[x1 x2] (products on the fly).
    for (int i = tid; i < IH * TW; i += 256) {
        int r = i >> 5;          // TW == 32
        int c = i & 31;
        float m1 = 0.f, m2 = 0.f, m11 = 0.f, m22 = 0.f, m12 = 0.f;
        #pragma unroll
        for (int k = 0; k < 11; k++) {
            float va = sA[r][c + k];
            float vb = sB[r][c + k];
            float gva = G[k] * va;
            float gvb = G[k] * vb;
            m1 += gva;
            m2 += gvb;
            m11 = fmaf(gva, va, m11);
            m22 = fmaf(gvb, vb, m22);
            m12 = fmaf(gva, vb, m12);
        }
        hbuf[0][r][c] = m1;
        hbuf[1][r][c] = m2;
        hbuf[2][r][c] = m11;
        hbuf[3][r][c] = m22;
        hbuf[4][r][c] = m12;
    }
    __syncthreads();

    // ---- stage 3: vertical 11-tap pass, register sliding window ----
    // Thread layout: 32 columns x 8 row-groups; each thread produces 4
    // consecutive output rows from 14 input rows (70 LDS for 4 outputs).
    float acc = 0.0f;
    {
        const int c = tid & 31;
        const int r0 = (tid >> 5) * 4;
        float s1[4]  = {0.f, 0.f, 0.f, 0.f};
        float s2[4]  = {0.f, 0.f, 0.f, 0.f};
        float s11[4] = {0.f, 0.f, 0.f, 0.f};
        float s22[4] = {0.f, 0.f, 0.f, 0.f};
        float s12[4] = {0.f, 0.f, 0.f, 0.f};
        #pragma unroll
        for (int t = 0; t < 14; t++) {
            float h1 = hbuf[0][r0 + t][c];
            float h2 = hbuf[1][r0 + t][c];
            float h3 = hbuf[2][r0 + t][c];
            float h4 = hbuf[3][r0 + t][c];
            float h5 = hbuf[4][r0 + t][c];
            #pragma unroll
            for (int j = 0; j < 4; j++) {
                int k = t - j;
                if (k >= 0 && k < 11) {
                    s1[j]  = fmaf(G[k], h1, s1[j]);
                    s2[j]  = fmaf(G[k], h2, s2[j]);
                    s11[j] = fmaf(G[k], h3, s11[j]);
                    s22[j] = fmaf(G[k], h4, s22[j]);
                    s12[j] = fmaf(G[k], h5, s12[j]);
                }
            }
        }
        const float C1 = 1e-4f;   // 0.01^2
        const float C2 = 9e-4f;   // 0.03^2
        #pragma unroll
        for (int j = 0; j < 4; j++) {
            float mu1 = s1[j], mu2 = s2[j];
            float mu1s = mu1 * mu1;
            float mu2s = mu2 * mu2;
            float mu12 = mu1 * mu2;
            float sg1  = s11[j] - mu1s;
            float sg2  = s22[j] - mu2s;
            float sg12 = s12[j] - mu12;
            float num = (2.0f * mu12 + C1) * (2.0f * sg12 + C2);
            float den = (mu1s + mu2s + C1) * (sg1 + sg2 + C2);
            acc += __fdividef(num, den);
        }
    }

    // ---- block reduction: warp shuffle -> smem -> one atomic per block ----
    #pragma unroll
    for (int o = 16; o > 0; o >>= 1)
        acc += __shfl_down_sync(0xffffffffu, acc, o);
    if ((tid & 31) == 0) red[tid >> 5] = acc;
    __syncthreads();
    if (tid == 0) {
        float s = red[0] + red[1] + red[2] + red[3]
                + red[4] + red[5] + red[6] + red[7];
        atomicAdd(&g_acc[scale], s);
    }
}

__global__ void finalize_kernel(float* __restrict__ out) {
    const float w[4] = {0.0448f, 0.2856f, 0.3001f, 0.2363f};
    float loss = 0.0f;
    float cnt = 48.0f * 512.0f * 512.0f;
    #pragma unroll
    for (int s = 0; s < 4; s++) {
        loss += w[s] * (1.0f - g_acc[s] / cnt);
        cnt *= 0.25f;
    }
    out[0] = loss;
}

extern "C" void kernel_launch(void* const* d_in, const int* in_sizes, int n_in,
                              void* d_out, int out_size) {
    const float* img1 = (const float*)d_in[0];
    const float* img2 = (const float*)d_in[1];
    float* out = (float*)d_out;

    init_acc_kernel<<<1, 32>>>();
    for (int s = 0; s < 4; s++) {
        int W = 512 >> s;
        dim3 grid(W / TW, W / TH, NPLANES);
        ssim_kernel<<<grid, 256>>>(s == 0 ? img1 : nullptr,
                                   s == 0 ? img2 : nullptr,
                                   s, W, (s < 3) ? 1 : 0);
    }
    finalize_kernel<<<1, 1>>>(out);
}

// round 2
// speedup vs baseline: 1.3771x; 1.3771x over previous
#include <cuda_runtime.h>

// MS-SSIM loss, 4 scales. Fused separable-Gaussian SSIM + 2x2 avg-pool.
// v2: float4 tile loads, register-sliding H-pass (LDS.128, FFMA-imm),
//     per-scale tile shapes so small scales get enough blocks.

#define NPLANES 48

// ---- scratch (static device globals; no allocations allowed) ----
__device__ float g_acc[4];
__device__ float g_p1a[48 * 256 * 256];
__device__ float g_p1b[48 * 256 * 256];
__device__ float g_p2a[48 * 128 * 128];
__device__ float g_p2b[48 * 128 * 128];
__device__ float g_p3a[48 * 64 * 64];
__device__ float g_p3b[48 * 64 * 64];

__global__ void init_acc_kernel() {
    if (threadIdx.x < 4) g_acc[threadIdx.x] = 0.0f;
}

// TW: tile width (output cols), TH: tile height, RPT: output rows per thread
// in the vertical pass, LWF: smem row pitch (floats) for the input tiles,
// HP: smem row pitch for the horizontal-pass buffer.
template<int TW, int TH, int RPT, int LWF, int HP>
__global__ void __launch_bounds__(TW * TH / RPT)
ssim_kernel(const float* __restrict__ A0, const float* __restrict__ B0,
            int scale, int W, int do_pool)
{
    constexpr int NT    = TW * TH / RPT;  // threads per block
    constexpr int IH    = TH + 10;        // input rows incl. halo
    constexpr int LW4   = TW / 4 + 4;     // float4 slots loaded per row
    constexpr int SLOTS = TW / 4;         // 4-wide output groups per row

    __shared__ __align__(16) float sA[IH][LWF];
    __shared__ __align__(16) float sB[IH][LWF];
    __shared__ float hbuf[5][IH][HP];
    __shared__ float red[NT / 32];

    // Gaussian(11, sigma=1.5), normalized; compile-time constants -> FFMA-imm.
    const float G[11] = {
        0.00102838f, 0.00759875f, 0.03600077f, 0.10936070f, 0.21300553f,
        0.26601172f,
        0.21300553f, 0.10936070f, 0.03600077f, 0.00759875f, 0.00102838f };

    const int H = W;
    const float* A;
    const float* B;
    switch (scale) {
        case 0:  A = A0;     B = B0;     break;
        case 1:  A = g_p1a;  B = g_p1b;  break;
        case 2:  A = g_p2a;  B = g_p2b;  break;
        default: A = g_p3a;  B = g_p3b;  break;
    }

    const int tx    = blockIdx.x * TW;
    const int ty    = blockIdx.y * TH;
    const int plane = blockIdx.z;
    const size_t pbase = (size_t)plane * (size_t)W * (size_t)H;
    const int tid = threadIdx.x;

    // ---- stage 1: aligned float4 loads of [ty-5..ty+TH+4] x [tx-8..tx-8+4*LW4) ----
    // smem col idx maps to gx = tx - 8 + idx. Out-of-image float4s are fully
    // in or fully out (gx0 % 4 == 0, W % 4 == 0) -> simple zero-fill.
    for (int i = tid; i < IH * LW4; i += NT) {
        int r = i / LW4;
        int s = i - r * LW4;
        int gy = ty + r - 5;
        int gx = tx + 4 * s - 8;
        float4 va = make_float4(0.f, 0.f, 0.f, 0.f);
        float4 vb = va;
        if ((unsigned)gy < (unsigned)H && (unsigned)gx <= (unsigned)(W - 4)) {
            size_t idx = pbase + (size_t)gy * W + gx;
            va = *reinterpret_cast<const float4*>(A + idx);
            vb = *reinterpret_cast<const float4*>(B + idx);
        }
        *reinterpret_cast<float4*>(&sA[r][4 * s]) = va;
        *reinterpret_cast<float4*>(&sB[r][4 * s]) = vb;
    }
    __syncthreads();

    // ---- fused 2x2 avg-pool for the next scale (tile is already in smem) ----
    if (do_pool) {
        constexpr int PW = TW / 2, PH = TH / 2;
        if (tid < PW * PH) {
            int pr = tid / PW;
            int pc = tid - pr * PW;
            int r = 5 + 2 * pr;       // smem row of gy = ty + 2*pr
            int c = 8 + 2 * pc;       // smem col of gx = tx + 2*pc
            float pa = 0.25f * (sA[r][c] + sA[r][c + 1] + sA[r + 1][c] + sA[r + 1][c + 1]);
            float pb = 0.25f * (sB[r][c] + sB[r][c + 1] + sB[r + 1][c] + sB[r + 1][c + 1]);
            int pW = W >> 1;
            size_t pidx = (size_t)plane * pW * pW
                        + (size_t)((ty >> 1) + pr) * pW + ((tx >> 1) + pc);
            float* PA;
            float* PB;
            switch (scale) {
                case 0:  PA = g_p1a; PB = g_p1b; break;
                case 1:  PA = g_p2a; PB = g_p2b; break;
                default: PA = g_p3a; PB = g_p3b; break;
            }
            PA[pidx] = pa;
            PB[pidx] = pb;
        }
    }

    // ---- stage 2: horizontal 11-tap pass, 4 outputs/thread, sliding window ----
    // Output col c uses smem cols c+3 .. c+13. For outputs c0..c0+3 we fetch
    // the 20-float window [c0 .. c0+19] as 5 aligned LDS.128 per image.
    for (int i = tid; i < IH * SLOTS; i += NT) {
        int r  = i / SLOTS;
        int sl = i - r * SLOTS;
        int c0 = 4 * sl;
        float wa[20], wb[20];
        #pragma unroll
        for (int q = 0; q < 5; q++) {
            float4 a4 = *reinterpret_cast<const float4*>(&sA[r][c0 + 4 * q]);
            float4 b4 = *reinterpret_cast<const float4*>(&sB[r][c0 + 4 * q]);
            wa[4 * q + 0] = a4.x; wa[4 * q + 1] = a4.y; wa[4 * q + 2] = a4.z; wa[4 * q + 3] = a4.w;
            wb[4 * q + 0] = b4.x; wb[4 * q + 1] = b4.y; wb[4 * q + 2] = b4.z; wb[4 * q + 3] = b4.w;
        }
        float m1[4]  = {0.f, 0.f, 0.f, 0.f};
        float m2[4]  = {0.f, 0.f, 0.f, 0.f};
        float m11[4] = {0.f, 0.f, 0.f, 0.f};
        float m22[4] = {0.f, 0.f, 0.f, 0.f};
        float m12[4] = {0.f, 0.f, 0.f, 0.f};
        #pragma unroll
        for (int t = 0; t < 14; t++) {
            float va = wa[t + 3];
            float vb = wb[t + 3];
            float aa = va * va;
            float bb = vb * vb;
            float ab = va * vb;
            #pragma unroll
            for (int j = 0; j < 4; j++) {
                int k = t - j;
                if (k >= 0 && k < 11) {
                    m1[j]  = fmaf(va, G[k], m1[j]);
                    m2[j]  = fmaf(vb, G[k], m2[j]);
                    m11[j] = fmaf(aa, G[k], m11[j]);
                    m22[j] = fmaf(bb, G[k], m22[j]);
                    m12[j] = fmaf(ab, G[k], m12[j]);
                }
            }
        }
        #pragma unroll
        for (int j = 0; j < 4; j++) {
            hbuf[0][r][c0 + j] = m1[j];
            hbuf[1][r][c0 + j] = m2[j];
            hbuf[2][r][c0 + j] = m11[j];
            hbuf[3][r][c0 + j] = m22[j];
            hbuf[4][r][c0 + j] = m12[j];
        }
    }
    __syncthreads();

    // ---- stage 3: vertical 11-tap pass, RPT outputs/thread, + SSIM map ----
    float acc = 0.0f;
    {
        const int c  = tid % TW;
        const int r0 = (tid / TW) * RPT;
        float s1[RPT], s2[RPT], s11[RPT], s22[RPT], s12[RPT];
        #pragma unroll
        for (int j = 0; j < RPT; j++) {
            s1[j] = s2[j] = s11[j] = s22[j] = s12[j] = 0.f;
        }
        #pragma unroll
        for (int t = 0; t < RPT + 10; t++) {
            float h1 = hbuf[0][r0 + t][c];
            float h2 = hbuf[1][r0 + t][c];
            float h3 = hbuf[2][r0 + t][c];
            float h4 = hbuf[3][r0 + t][c];
            float h5 = hbuf[4][r0 + t][c];
            #pragma unroll
            for (int j = 0; j < RPT; j++) {
                int k = t - j;
                if (k >= 0 && k < 11) {
                    s1[j]  = fmaf(h1, G[k], s1[j]);
                    s2[j]  = fmaf(h2, G[k], s2[j]);
                    s11[j] = fmaf(h3, G[k], s11[j]);
                    s22[j] = fmaf(h4, G[k], s22[j]);
                    s12[j] = fmaf(h5, G[k], s12[j]);
                }
            }
        }
        const float C1 = 1e-4f;   // 0.01^2
        const float C2 = 9e-4f;   // 0.03^2
        #pragma unroll
        for (int j = 0; j < RPT; j++) {
            float mu1 = s1[j], mu2 = s2[j];
            float mu1s = mu1 * mu1;
            float mu2s = mu2 * mu2;
            float mu12 = mu1 * mu2;
            float sg1  = s11[j] - mu1s;
            float sg2  = s22[j] - mu2s;
            float sg12 = s12[j] - mu12;
            float num = (2.0f * mu12 + C1) * (2.0f * sg12 + C2);
            float den = (mu1s + mu2s + C1) * (sg1 + sg2 + C2);
            acc += __fdividef(num, den);
        }
    }

    // ---- block reduction: warp shuffle -> smem -> one atomic per block ----
    #pragma unroll
    for (int o = 16; o > 0; o >>= 1)
        acc += __shfl_down_sync(0xffffffffu, acc, o);
    if ((tid & 31) == 0) red[tid >> 5] = acc;
    __syncthreads();
    if (tid == 0) {
        float s = 0.f;
        #pragma unroll
        for (int w = 0; w < NT / 32; w++) s += red[w];
        atomicAdd(&g_acc[scale], s);
    }
}

__global__ void finalize_kernel(float* __restrict__ out) {
    const float w[4] = {0.0448f, 0.2856f, 0.3001f, 0.2363f};
    float loss = 0.0f;
    float cnt = 48.0f * 512.0f * 512.0f;
    #pragma unroll
    for (int s = 0; s < 4; s++) {
        loss += w[s] * (1.0f - g_acc[s] / cnt);
        cnt *= 0.25f;
    }
    out[0] = loss;
}

extern "C" void kernel_launch(void* const* d_in, const int* in_sizes, int n_in,
                              void* d_out, int out_size) {
    const float* img1 = (const float*)d_in[0];
    const float* img2 = (const float*)d_in[1];
    float* out = (float*)d_out;

    init_acc_kernel<<<1, 32>>>();

    // scale 0: 512x512, 32x32 tiles, 256 thr
    ssim_kernel<32, 32, 4, 48, 33><<<dim3(16, 16, NPLANES), 256>>>(img1, img2, 0, 512, 1);
    // scale 1: 256x256, 32x32 tiles
    ssim_kernel<32, 32, 4, 48, 33><<<dim3(8, 8, NPLANES), 256>>>(nullptr, nullptr, 1, 256, 1);
    // scale 2: 128x128, 32x16 tiles (more blocks, shallower critical path)
    ssim_kernel<32, 16, 2, 48, 33><<<dim3(4, 8, NPLANES), 256>>>(nullptr, nullptr, 2, 128, 1);
    // scale 3: 64x64, 16x16 tiles
    ssim_kernel<16, 16, 2, 48, 24><<<dim3(4, 4, NPLANES), 128>>>(nullptr, nullptr, 3, 64, 0);

    finalize_kernel<<<1, 1>>>(out);
}

// round 3
// speedup vs baseline: 1.3980x; 1.0151x over previous
#include <cuda_runtime.h>

// MS-SSIM loss, 4 scales. Fused separable-Gaussian SSIM + 2x2 avg-pool.
// v3: packed f32x2 math (FFMA2) for the channel pairs (mu1,mu2)/(E11,E22),
//     paired hbuf layout (LDS.64/STS.64), float4 tile loads.

#define NPLANES 48

// ---- scratch (static device globals; no allocations allowed) ----
__device__ float g_acc[4];
__device__ float g_p1a[48 * 256 * 256];
__device__ float g_p1b[48 * 256 * 256];
__device__ float g_p2a[48 * 128 * 128];
__device__ float g_p2b[48 * 128 * 128];
__device__ float g_p3a[48 * 64 * 64];
__device__ float g_p3b[48 * 64 * 64];

__global__ void init_acc_kernel() {
    if (threadIdx.x < 4) g_acc[threadIdx.x] = 0.0f;
}

// ---- packed f32x2 helpers (sm_103a FFMA2 path, PTX-only) ----
__device__ __forceinline__ unsigned long long pack2(float lo, float hi) {
    unsigned long long r;
    asm("mov.b64 %0, {%1, %2};" : "=l"(r) : "f"(lo), "f"(hi));
    return r;
}
__device__ __forceinline__ void unpack2(unsigned long long v, float& lo, float& hi) {
    asm("mov.b64 {%0, %1}, %2;" : "=f"(lo), "=f"(hi) : "l"(v));
}
__device__ __forceinline__ void ffma2(unsigned long long& acc,
                                      unsigned long long a, unsigned long long b) {
    asm("fma.rn.f32x2 %0, %1, %2, %0;" : "+l"(acc) : "l"(a), "l"(b));
}
__device__ __forceinline__ unsigned long long fmul2(unsigned long long a,
                                                    unsigned long long b) {
    unsigned long long d;
    asm("mul.rn.f32x2 %0, %1, %2;" : "=l"(d) : "l"(a), "l"(b));
    return d;
}

// Gaussian(11, sigma=1.5), normalized.
#define G_LIST { \
    0.00102838f, 0.00759875f, 0.03600077f, 0.10936070f, 0.21300553f, \
    0.26601172f, \
    0.21300553f, 0.10936070f, 0.03600077f, 0.00759875f, 0.00102838f }

// TW: tile width, TH: tile height, RPT: rows/thread in V-pass,
// LWF: smem pitch (floats) for input tiles, HP: hbuf pitch (elements).
template<int TW, int TH, int RPT, int LWF, int HP>
__global__ void __launch_bounds__(TW * TH / RPT)
ssim_kernel(const float* __restrict__ A0, const float* __restrict__ B0,
            int scale, int W, int do_pool)
{
    constexpr int NT    = TW * TH / RPT;
    constexpr int IH    = TH + 10;
    constexpr int LW4   = TW / 4 + 4;
    constexpr int SLOTS = TW / 4;

    __shared__ __align__(16) float sA[IH][LWF];
    __shared__ __align__(16) float sB[IH][LWF];
    __shared__ unsigned long long h12[IH][HP];    // (mu1, mu2) packed
    __shared__ unsigned long long h1122[IH][HP];  // (E[x^2], E[y^2]) packed
    __shared__ float hx[IH][HP];                  // E[x*y]
    __shared__ float red[NT / 32];

    const float G[11] = G_LIST;

    const int H = W;
    const float* A;
    const float* B;
    switch (scale) {
        case 0:  A = A0;     B = B0;     break;
        case 1:  A = g_p1a;  B = g_p1b;  break;
        case 2:  A = g_p2a;  B = g_p2b;  break;
        default: A = g_p3a;  B = g_p3b;  break;
    }

    const int tx    = blockIdx.x * TW;
    const int ty    = blockIdx.y * TH;
    const int plane = blockIdx.z;
    const size_t pbase = (size_t)plane * (size_t)W * (size_t)H;
    const int tid = threadIdx.x;

    // ---- stage 1: aligned float4 tile loads, zero-padded halo ----
    for (int i = tid; i < IH * LW4; i += NT) {
        int r = i / LW4;
        int s = i - r * LW4;
        int gy = ty + r - 5;
        int gx = tx + 4 * s - 8;
        float4 va = make_float4(0.f, 0.f, 0.f, 0.f);
        float4 vb = va;
        if ((unsigned)gy < (unsigned)H && (unsigned)gx <= (unsigned)(W - 4)) {
            size_t idx = pbase + (size_t)gy * W + gx;
            va = *reinterpret_cast<const float4*>(A + idx);
            vb = *reinterpret_cast<const float4*>(B + idx);
        }
        *reinterpret_cast<float4*>(&sA[r][4 * s]) = va;
        *reinterpret_cast<float4*>(&sB[r][4 * s]) = vb;
    }
    __syncthreads();

    // ---- fused 2x2 avg-pool for the next scale ----
    if (do_pool) {
        constexpr int PW = TW / 2, PH = TH / 2;
        if (tid < PW * PH) {
            int pr = tid / PW;
            int pc = tid - pr * PW;
            int r = 5 + 2 * pr;
            int c = 8 + 2 * pc;
            float pa = 0.25f * (sA[r][c] + sA[r][c + 1] + sA[r + 1][c] + sA[r + 1][c + 1]);
            float pb = 0.25f * (sB[r][c] + sB[r][c + 1] + sB[r + 1][c] + sB[r + 1][c + 1]);
            int pW = W >> 1;
            size_t pidx = (size_t)plane * pW * pW
                        + (size_t)((ty >> 1) + pr) * pW + ((tx >> 1) + pc);
            float* PA;
            float* PB;
            switch (scale) {
                case 0:  PA = g_p1a; PB = g_p1b; break;
                case 1:  PA = g_p2a; PB = g_p2b; break;
                default: PA = g_p3a; PB = g_p3b; break;
            }
            PA[pidx] = pa;
            PB[pidx] = pb;
        }
    }

    // ---- stage 2: horizontal 11-tap pass, 4 outputs/thread, packed math ----
    {
        unsigned long long g2[11];
        #pragma unroll
        for (int k = 0; k < 11; k++) g2[k] = pack2(G[k], G[k]);

        for (int i = tid; i < IH * SLOTS; i += NT) {
            int r  = i / SLOTS;
            int sl = i - r * SLOTS;
            int c0 = 4 * sl;
            float wa[20], wb[20];
            #pragma unroll
            for (int q = 0; q < 5; q++) {
                float4 a4 = *reinterpret_cast<const float4*>(&sA[r][c0 + 4 * q]);
                float4 b4 = *reinterpret_cast<const float4*>(&sB[r][c0 + 4 * q]);
                wa[4*q+0] = a4.x; wa[4*q+1] = a4.y; wa[4*q+2] = a4.z; wa[4*q+3] = a4.w;
                wb[4*q+0] = b4.x; wb[4*q+1] = b4.y; wb[4*q+2] = b4.z; wb[4*q+3] = b4.w;
            }
            unsigned long long m12p[4], m1122p[4];
            float mx[4];
            #pragma unroll
            for (int j = 0; j < 4; j++) { m12p[j] = 0ull; m1122p[j] = 0ull; mx[j] = 0.f; }
            #pragma unroll
            for (int t = 0; t < 14; t++) {
                float va = wa[t + 3];
                float vb = wb[t + 3];
                unsigned long long vab  = pack2(va, vb);
                unsigned long long aabb = fmul2(vab, vab);
                float ab = va * vb;
                #pragma unroll
                for (int j = 0; j < 4; j++) {
                    int k = t - j;
                    if (k >= 0 && k < 11) {
                        ffma2(m12p[j],   vab,  g2[k]);
                        ffma2(m1122p[j], aabb, g2[k]);
                        mx[j] = fmaf(ab, G[k], mx[j]);
                    }
                }
            }
            #pragma unroll
            for (int j = 0; j < 4; j++) {
                h12[r][c0 + j]   = m12p[j];
                h1122[r][c0 + j] = m1122p[j];
                hx[r][c0 + j]    = mx[j];
            }
        }
    }
    __syncthreads();

    // ---- stage 3: vertical 11-tap pass (packed), SSIM map, reduce ----
    float acc = 0.0f;
    {
        unsigned long long g2[11];
        #pragma unroll
        for (int k = 0; k < 11; k++) g2[k] = pack2(G[k], G[k]);

        const int c  = tid % TW;
        const int r0 = (tid / TW) * RPT;
        unsigned long long s12p[RPT], s1122p[RPT];
        float sx[RPT];
        #pragma unroll
        for (int j = 0; j < RPT; j++) { s12p[j] = 0ull; s1122p[j] = 0ull; sx[j] = 0.f; }

        #pragma unroll
        for (int t = 0; t < RPT + 10; t++) {
            unsigned long long v12   = h12[r0 + t][c];
            unsigned long long v1122 = h1122[r0 + t][c];
            float vx = hx[r0 + t][c];
            #pragma unroll
            for (int j = 0; j < RPT; j++) {
                int k = t - j;
                if (k >= 0 && k < 11) {
                    ffma2(s12p[j],   v12,   g2[k]);
                    ffma2(s1122p[j], v1122, g2[k]);
                    sx[j] = fmaf(vx, G[k], sx[j]);
                }
            }
        }
        const float C1 = 1e-4f;
        const float C2 = 9e-4f;
        #pragma unroll
        for (int j = 0; j < RPT; j++) {
            float mu1, mu2, e11, e22;
            unpack2(s12p[j], mu1, mu2);
            unpack2(s1122p[j], e11, e22);
            float mu1s = mu1 * mu1;
            float mu2s = mu2 * mu2;
            float mu12 = mu1 * mu2;
            float sg1  = e11 - mu1s;
            float sg2  = e22 - mu2s;
            float sg12 = sx[j] - mu12;
            float num = (2.0f * mu12 + C1) * (2.0f * sg12 + C2);
            float den = (mu1s + mu2s + C1) * (sg1 + sg2 + C2);
            acc += __fdividef(num, den);
        }
    }

    // ---- block reduction -> one atomic per block ----
    #pragma unroll
    for (int o = 16; o > 0; o >>= 1)
        acc += __shfl_down_sync(0xffffffffu, acc, o);
    if ((tid & 31) == 0) red[tid >> 5] = acc;
    __syncthreads();
    if (tid == 0) {
        float s = 0.f;
        #pragma unroll
        for (int w = 0; w < NT / 32; w++) s += red[w];
        atomicAdd(&g_acc[scale], s);
    }
}

__global__ void finalize_kernel(float* __restrict__ out) {
    const float w[4] = {0.0448f, 0.2856f, 0.3001f, 0.2363f};
    float loss = 0.0f;
    float cnt = 48.0f * 512.0f * 512.0f;
    #pragma unroll
    for (int s = 0; s < 4; s++) {
        loss += w[s] * (1.0f - g_acc[s] / cnt);
        cnt *= 0.25f;
    }
    out[0] = loss;
}

extern "C" void kernel_launch(void* const* d_in, const int* in_sizes, int n_in,
                              void* d_out, int out_size) {
    const float* img1 = (const float*)d_in[0];
    const float* img2 = (const float*)d_in[1];
    float* out = (float*)d_out;

    init_acc_kernel<<<1, 32>>>();

    // scale 0: 512x512, 32x32 tiles, 256 thr
    ssim_kernel<32, 32, 4, 48, 33><<<dim3(16, 16, NPLANES), 256>>>(img1, img2, 0, 512, 1);
    // scale 1: 256x256
    ssim_kernel<32, 32, 4, 48, 33><<<dim3(8, 8, NPLANES), 256>>>(nullptr, nullptr, 1, 256, 1);
    // scale 2: 128x128, 32x16 tiles
    ssim_kernel<32, 16, 2, 48, 33><<<dim3(4, 8, NPLANES), 256>>>(nullptr, nullptr, 2, 128, 1);
    // scale 3: 64x64, 16x16 tiles
    ssim_kernel<16, 16, 2, 48, 24><<<dim3(4, 4, NPLANES), 128>>>(nullptr, nullptr, 3, 64, 0);

    finalize_kernel<<<1, 1>>>(out);
}